// round 2
// baseline (speedup 1.0000x reference)
#include <cuda_runtime.h>
#include <cuda_bf16.h>
#include <stdint.h>

// Problem constants
#define SQ   2048   // sequence length S
#define DM   1024   // model dim D
#define NH   16     // heads H
#define HDD  64     // head dim
#define NK   64     // neighbors K

// Scratch (no cudaMalloc allowed): h and fused buffers, 8 MB each
__device__ float g_h[SQ * DM];
__device__ float g_fused[SQ * DM];

// ---------------------------------------------------------------------------
// NT SGEMM: C[m,n] = sum_k A[m,k] * B[n,k]  (+ optional bias[n] + resid[m,n])
// M=2048, N=1024, Kdim=1024. Tiles: 128x128x16, 256 threads, 8x8 per thread.
// ---------------------------------------------------------------------------
template <bool EPI>
__global__ __launch_bounds__(256)
void sgemm_nt(const float* __restrict__ A,
              const float* __restrict__ B,
              float* __restrict__ C,
              const float* __restrict__ bias,
              const float* __restrict__ resid)
{
    constexpr int BM = 128, BN = 128, BK = 16;
    constexpr int KD = 1024;   // inner dim
    constexpr int NC = 1024;   // C column count (= N total)

    __shared__ float As[BK][BM + 4];
    __shared__ float Bs[BK][BN + 4];

    const int t  = threadIdx.x;
    const int bm = blockIdx.y;   // M tile
    const int bn = blockIdx.x;   // N tile
    const int tx = t & 15;       // 0..15
    const int ty = t >> 4;       // 0..15

    float acc[8][8];
#pragma unroll
    for (int i = 0; i < 8; i++)
#pragma unroll
        for (int j = 0; j < 8; j++) acc[i][j] = 0.f;

    const float* Abase = A + (size_t)(bm * BM) * KD;
    const float* Bbase = B + (size_t)(bn * BN) * KD;

    for (int k0 = 0; k0 < KD; k0 += BK) {
        // Load A tile: 128 rows x 16 cols = 512 float4; 2 per thread
#pragma unroll
        for (int f = t; f < 512; f += 256) {
            const int row  = f >> 2;
            const int col4 = (f & 3) << 2;
            float4 v = *(const float4*)(Abase + (size_t)row * KD + k0 + col4);
            As[col4 + 0][row] = v.x;
            As[col4 + 1][row] = v.y;
            As[col4 + 2][row] = v.z;
            As[col4 + 3][row] = v.w;
        }
#pragma unroll
        for (int f = t; f < 512; f += 256) {
            const int row  = f >> 2;
            const int col4 = (f & 3) << 2;
            float4 v = *(const float4*)(Bbase + (size_t)row * KD + k0 + col4);
            Bs[col4 + 0][row] = v.x;
            Bs[col4 + 1][row] = v.y;
            Bs[col4 + 2][row] = v.z;
            Bs[col4 + 3][row] = v.w;
        }
        __syncthreads();

#pragma unroll
        for (int kk = 0; kk < BK; kk++) {
            float4 a0 = *(const float4*)&As[kk][ty * 8];
            float4 a1 = *(const float4*)&As[kk][ty * 8 + 4];
            float4 b0 = *(const float4*)&Bs[kk][tx * 8];
            float4 b1 = *(const float4*)&Bs[kk][tx * 8 + 4];
            const float a[8] = {a0.x, a0.y, a0.z, a0.w, a1.x, a1.y, a1.z, a1.w};
            const float b[8] = {b0.x, b0.y, b0.z, b0.w, b1.x, b1.y, b1.z, b1.w};
#pragma unroll
            for (int i = 0; i < 8; i++)
#pragma unroll
                for (int j = 0; j < 8; j++)
                    acc[i][j] = fmaf(a[i], b[j], acc[i][j]);
        }
        __syncthreads();
    }

    // Epilogue + store (float4)
#pragma unroll
    for (int i = 0; i < 8; i++) {
        const int row = bm * BM + ty * 8 + i;
#pragma unroll
        for (int j4 = 0; j4 < 8; j4 += 4) {
            const int col = bn * BN + tx * 8 + j4;
            float4 v = make_float4(acc[i][j4], acc[i][j4 + 1],
                                   acc[i][j4 + 2], acc[i][j4 + 3]);
            if (EPI) {
                float4 bv = *(const float4*)(bias + col);
                float4 rv = *(const float4*)(resid + (size_t)row * NC + col);
                v.x += bv.x + rv.x;
                v.y += bv.y + rv.y;
                v.z += bv.z + rv.z;
                v.w += bv.w + rv.w;
            }
            *(float4*)(C + (size_t)row * NC + col) = v;
        }
    }
}

// ---------------------------------------------------------------------------
// Attention-fusion kernel: one block of 64 threads per (token s, head hh).
// Thread t = neighbor index during score phase; = head-dim index in output.
// Neighbor tile staged in SMEM transposed: nbT[d][k], pad +1 -> conflict-free.
// routes read as int32 (harness materializes int64 as int32); mask to [0,SQ)
// so a dtype surprise degrades to a rel_err failure, not an illegal access.
// ---------------------------------------------------------------------------
__global__ __launch_bounds__(64)
void attn_kernel(const float* __restrict__ hbuf,
                 const int32_t* __restrict__ routes,
                 float* __restrict__ fused)
{
    const int s  = blockIdx.x;
    const int hh = blockIdx.y;
    const int t  = threadIdx.x;   // 0..63

    __shared__ float nbT[HDD][NK + 1];  // [d][k]
    __shared__ float q[HDD];
    __shared__ float sc[NK];

    // Load query head
    q[t] = hbuf[(size_t)s * DM + hh * HDD + t];
    __syncthreads();

    // Each thread gathers one neighbor row (64 contiguous floats from L2),
    // computes the dot with q, and stages the row transposed into SMEM.
    const int r = routes[(size_t)s * NK + t] & (SQ - 1);
    const float* np = hbuf + (size_t)r * DM + hh * HDD;
    float dot = 0.f;
#pragma unroll
    for (int d0 = 0; d0 < HDD; d0 += 4) {
        float4 v  = *(const float4*)(np + d0);
        float4 qv = *(const float4*)(q + d0);
        dot = fmaf(v.x, qv.x, dot);
        dot = fmaf(v.y, qv.y, dot);
        dot = fmaf(v.z, qv.z, dot);
        dot = fmaf(v.w, qv.w, dot);
        nbT[d0 + 0][t] = v.x;
        nbT[d0 + 1][t] = v.y;
        nbT[d0 + 2][t] = v.z;
        nbT[d0 + 3][t] = v.w;
    }
    sc[t] = dot * 0.125f;   // 1/sqrt(64)
    __syncthreads();

    // Softmax numerator for this thread's k
    float mx = -1e30f;
#pragma unroll
    for (int k = 0; k < NK; k++) mx = fmaxf(mx, sc[k]);
    const float w = expf(sc[t] - mx);
    __syncthreads();
    sc[t] = w;
    __syncthreads();

    // Output: thread t owns head-dim d = t
    float sum = 0.f, accv = 0.f;
#pragma unroll
    for (int k = 0; k < NK; k++) {
        const float wk = sc[k];
        sum  += wk;
        accv  = fmaf(wk, nbT[t][k], accv);
    }
    fused[(size_t)s * DM + hh * HDD + t] = accv / sum;
}

// ---------------------------------------------------------------------------
// Launch: resolve inputs by element count (robust to metadata ordering).
//   x: 2048*1024 = 2097152, routes: 2048*64 = 131072,
//   W_in/W_out: 1024*1024 = 1048576 (first-seen = W_in), b_out: 1024
// ---------------------------------------------------------------------------
extern "C" void kernel_launch(void* const* d_in, const int* in_sizes, int n_in,
                              void* d_out, int out_size)
{
    const float*   x      = nullptr;
    const int32_t* routes = nullptr;
    const float*   W_in   = nullptr;
    const float*   W_out  = nullptr;
    const float*   b_out  = nullptr;

    for (int i = 0; i < n_in; i++) {
        const int sz = in_sizes[i];
        if      (sz == SQ * DM)  { x = (const float*)d_in[i]; }
        else if (sz == SQ * NK)  { routes = (const int32_t*)d_in[i]; }
        else if (sz == DM * DM)  { if (!W_in) W_in = (const float*)d_in[i];
                                   else       W_out = (const float*)d_in[i]; }
        else if (sz == DM)       { b_out = (const float*)d_in[i]; }
    }
    float* out = (float*)d_out;

    float* hbuf = nullptr;
    float* fbuf = nullptr;
    cudaGetSymbolAddress((void**)&hbuf, g_h);
    cudaGetSymbolAddress((void**)&fbuf, g_fused);

    dim3 gGemm(DM / 128, SQ / 128);   // (8, 16)

    // h = x @ W_in^T
    sgemm_nt<false><<<gGemm, 256>>>(x, W_in, hbuf, nullptr, nullptr);

    // fused = softmax(q . neigh / sqrt(hd)) @ neigh, gathered on the fly
    attn_kernel<<<dim3(SQ, NH), 64>>>(hbuf, routes, fbuf);

    // out = fused @ W_out^T + b_out + x
    sgemm_nt<true><<<gGemm, 256>>>(fbuf, W_out, out, b_out, x);
}

// round 3
// speedup vs baseline: 1.0931x; 1.0931x over previous
#include <cuda_runtime.h>
#include <cuda_bf16.h>
#include <stdint.h>

// Problem constants
#define SQ   2048
#define DM   1024
#define NH   16
#define HDD  64
#define NK   64

__device__ float g_h[SQ * DM];
__device__ float g_fused[SQ * DM];

// ---------------------------------------------------------------------------
// 3xTF32 NT GEMM via mma.sync.m16n8k8: C[m,n] = sum_k A[m,k]*B[n,k]
// Tiles: 128x128xBK16, 256 threads (8 warps, 2x4 m-by-n), warp tile 64x32,
// 4x4 mma tiles per warp. hi/lo tf32 split restores ~fp32 accuracy.
// smem row stride 20 floats -> conflict-free a/b fragment LDS.
// ---------------------------------------------------------------------------
__device__ __forceinline__ uint32_t f2tf32(float v) {
    uint32_t r;
    asm("cvt.rna.tf32.f32 %0, %1;" : "=r"(r) : "f"(v));
    return r;
}
__device__ __forceinline__ void cvt4(float4 v, float4& hi, float4& lo) {
    uint32_t hx = f2tf32(v.x), hy = f2tf32(v.y), hz = f2tf32(v.z), hw = f2tf32(v.w);
    hi = make_float4(__uint_as_float(hx), __uint_as_float(hy),
                     __uint_as_float(hz), __uint_as_float(hw));
    lo = make_float4(__uint_as_float(f2tf32(v.x - hi.x)),
                     __uint_as_float(f2tf32(v.y - hi.y)),
                     __uint_as_float(f2tf32(v.z - hi.z)),
                     __uint_as_float(f2tf32(v.w - hi.w)));
}
__device__ __forceinline__ void mma_tf32(float* c, const uint32_t* a, const uint32_t* b) {
    asm volatile(
        "mma.sync.aligned.m16n8k8.row.col.f32.tf32.tf32.f32 "
        "{%0,%1,%2,%3}, {%4,%5,%6,%7}, {%8,%9}, {%0,%1,%2,%3};"
        : "+f"(c[0]), "+f"(c[1]), "+f"(c[2]), "+f"(c[3])
        : "r"(a[0]), "r"(a[1]), "r"(a[2]), "r"(a[3]), "r"(b[0]), "r"(b[1]));
}

template <bool EPI>
__global__ __launch_bounds__(256, 1)
void gemm_tf32x3(const float* __restrict__ A,
                 const float* __restrict__ B,
                 float* __restrict__ C,
                 const float* __restrict__ bias,
                 const float* __restrict__ resid)
{
    constexpr int KD = 1024, NC = 1024, SK = 20;  // SK: padded k-stride

    __shared__ float As_hi[128][SK], As_lo[128][SK];
    __shared__ float Bs_hi[128][SK], Bs_lo[128][SK];

    const int t    = threadIdx.x;
    const int lane = t & 31;
    const int w    = t >> 5;
    const int wm   = w >> 2;          // 0..1 -> rows wm*64
    const int wn   = w & 3;           // 0..3 -> cols wn*32
    const int bm   = blockIdx.y;
    const int bn   = blockIdx.x;
    const int r4   = lane >> 2;       // 0..7
    const int c4   = lane & 3;        // 0..3

    float acc[4][4][4];
#pragma unroll
    for (int i = 0; i < 4; i++)
#pragma unroll
        for (int j = 0; j < 4; j++)
#pragma unroll
            for (int q = 0; q < 4; q++) acc[i][j][q] = 0.f;

    const float* Abase = A + (size_t)(bm * 128) * KD;
    const float* Bbase = B + (size_t)(bn * 128) * KD;

    for (int k0 = 0; k0 < KD; k0 += 16) {
        // Stage: load 128x16 fp32 tiles of A and B, split hi/lo into smem.
#pragma unroll
        for (int i = 0; i < 2; i++) {
            const int f    = t + i * 256;       // 0..511
            const int row  = f >> 2;
            const int col4 = (f & 3) << 2;
            float4 va = *(const float4*)(Abase + (size_t)row * KD + k0 + col4);
            float4 hi, lo;
            cvt4(va, hi, lo);
            *(float4*)&As_hi[row][col4] = hi;
            *(float4*)&As_lo[row][col4] = lo;
            float4 vb = *(const float4*)(Bbase + (size_t)row * KD + k0 + col4);
            cvt4(vb, hi, lo);
            *(float4*)&Bs_hi[row][col4] = hi;
            *(float4*)&Bs_lo[row][col4] = lo;
        }
        __syncthreads();

#pragma unroll
        for (int k8 = 0; k8 < 16; k8 += 8) {
            // B fragments for 4 n-tiles (hi & lo)
            uint32_t bh[4][2], bl[4][2];
#pragma unroll
            for (int nt = 0; nt < 4; nt++) {
                const int n0 = wn * 32 + nt * 8 + r4;
                bh[nt][0] = *(const uint32_t*)&Bs_hi[n0][k8 + c4];
                bh[nt][1] = *(const uint32_t*)&Bs_hi[n0][k8 + c4 + 4];
                bl[nt][0] = *(const uint32_t*)&Bs_lo[n0][k8 + c4];
                bl[nt][1] = *(const uint32_t*)&Bs_lo[n0][k8 + c4 + 4];
            }
#pragma unroll
            for (int mt = 0; mt < 4; mt++) {
                const int m0 = wm * 64 + mt * 16;
                uint32_t ah[4], al[4];
                ah[0] = *(const uint32_t*)&As_hi[m0 + r4    ][k8 + c4];
                ah[1] = *(const uint32_t*)&As_hi[m0 + r4 + 8][k8 + c4];
                ah[2] = *(const uint32_t*)&As_hi[m0 + r4    ][k8 + c4 + 4];
                ah[3] = *(const uint32_t*)&As_hi[m0 + r4 + 8][k8 + c4 + 4];
                al[0] = *(const uint32_t*)&As_lo[m0 + r4    ][k8 + c4];
                al[1] = *(const uint32_t*)&As_lo[m0 + r4 + 8][k8 + c4];
                al[2] = *(const uint32_t*)&As_lo[m0 + r4    ][k8 + c4 + 4];
                al[3] = *(const uint32_t*)&As_lo[m0 + r4 + 8][k8 + c4 + 4];
#pragma unroll
                for (int nt = 0; nt < 4; nt++) {
                    mma_tf32(acc[mt][nt], ah, bh[nt]);   // hi*hi
                    mma_tf32(acc[mt][nt], ah, bl[nt]);   // hi*lo
                    mma_tf32(acc[mt][nt], al, bh[nt]);   // lo*hi
                }
            }
        }
        __syncthreads();
    }

    // Epilogue
#pragma unroll
    for (int mt = 0; mt < 4; mt++) {
#pragma unroll
        for (int nt = 0; nt < 4; nt++) {
            const int row0 = bm * 128 + wm * 64 + mt * 16 + r4;
            const int col  = bn * 128 + wn * 32 + nt * 8 + c4 * 2;
            float2 v0 = make_float2(acc[mt][nt][0], acc[mt][nt][1]);
            float2 v1 = make_float2(acc[mt][nt][2], acc[mt][nt][3]);
            if (EPI) {
                float2 bv = *(const float2*)(bias + col);
                float2 r0 = *(const float2*)(resid + (size_t)row0 * NC + col);
                float2 r1 = *(const float2*)(resid + (size_t)(row0 + 8) * NC + col);
                v0.x += bv.x + r0.x;  v0.y += bv.y + r0.y;
                v1.x += bv.x + r1.x;  v1.y += bv.y + r1.y;
            }
            *(float2*)(C + (size_t)row0 * NC + col)       = v0;
            *(float2*)(C + (size_t)(row0 + 8) * NC + col) = v1;
        }
    }
}

// ---------------------------------------------------------------------------
// Attention-fusion kernel (unchanged from R2 — known correct; profile next).
// ---------------------------------------------------------------------------
__global__ __launch_bounds__(64)
void attn_kernel(const float* __restrict__ hbuf,
                 const int32_t* __restrict__ routes,
                 float* __restrict__ fused)
{
    const int s  = blockIdx.x;
    const int hh = blockIdx.y;
    const int t  = threadIdx.x;

    __shared__ float nbT[HDD][NK + 1];
    __shared__ float q[HDD];
    __shared__ float sc[NK];

    q[t] = hbuf[(size_t)s * DM + hh * HDD + t];
    __syncthreads();

    const int r = routes[(size_t)s * NK + t] & (SQ - 1);
    const float* np = hbuf + (size_t)r * DM + hh * HDD;
    float dot = 0.f;
#pragma unroll
    for (int d0 = 0; d0 < HDD; d0 += 4) {
        float4 v  = *(const float4*)(np + d0);
        float4 qv = *(const float4*)(q + d0);
        dot = fmaf(v.x, qv.x, dot);
        dot = fmaf(v.y, qv.y, dot);
        dot = fmaf(v.z, qv.z, dot);
        dot = fmaf(v.w, qv.w, dot);
        nbT[d0 + 0][t] = v.x;
        nbT[d0 + 1][t] = v.y;
        nbT[d0 + 2][t] = v.z;
        nbT[d0 + 3][t] = v.w;
    }
    sc[t] = dot * 0.125f;
    __syncthreads();

    float mx = -1e30f;
#pragma unroll
    for (int k = 0; k < NK; k++) mx = fmaxf(mx, sc[k]);
    const float w = expf(sc[t] - mx);
    __syncthreads();
    sc[t] = w;
    __syncthreads();

    float sum = 0.f, accv = 0.f;
#pragma unroll
    for (int k = 0; k < NK; k++) {
        const float wk = sc[k];
        sum  += wk;
        accv  = fmaf(wk, nbT[t][k], accv);
    }
    fused[(size_t)s * DM + hh * HDD + t] = accv / sum;
}

// ---------------------------------------------------------------------------
// Launch: resolve inputs by element count.
// ---------------------------------------------------------------------------
extern "C" void kernel_launch(void* const* d_in, const int* in_sizes, int n_in,
                              void* d_out, int out_size)
{
    const float*   x      = nullptr;
    const int32_t* routes = nullptr;
    const float*   W_in   = nullptr;
    const float*   W_out  = nullptr;
    const float*   b_out  = nullptr;

    for (int i = 0; i < n_in; i++) {
        const int sz = in_sizes[i];
        if      (sz == SQ * DM)  { x = (const float*)d_in[i]; }
        else if (sz == SQ * NK)  { routes = (const int32_t*)d_in[i]; }
        else if (sz == DM * DM)  { if (!W_in) W_in = (const float*)d_in[i];
                                   else       W_out = (const float*)d_in[i]; }
        else if (sz == DM)       { b_out = (const float*)d_in[i]; }
    }
    float* out = (float*)d_out;

    float* hbuf = nullptr;
    float* fbuf = nullptr;
    cudaGetSymbolAddress((void**)&hbuf, g_h);
    cudaGetSymbolAddress((void**)&fbuf, g_fused);

    dim3 gGemm(DM / 128, SQ / 128);   // (8, 16)

    gemm_tf32x3<false><<<gGemm, 256>>>(x, W_in, hbuf, nullptr, nullptr);
    attn_kernel<<<dim3(SQ, NH), 64>>>(hbuf, routes, fbuf);
    gemm_tf32x3<true><<<gGemm, 256>>>(fbuf, W_out, out, b_out, x);
}

// round 4
// speedup vs baseline: 1.4824x; 1.3562x over previous
#include <cuda_runtime.h>
#include <cuda_bf16.h>
#include <stdint.h>

#define SQ   2048
#define DM   1024
#define NH   16
#define HDD  64
#define NK   64

// fp32 hidden buffer (attn gathers from this)
__device__ float g_h[SQ * DM];
// bf16 hi/lo operand copies
__device__ __nv_bfloat16 g_xh[SQ * DM], g_xl[SQ * DM];
__device__ __nv_bfloat16 g_wih[DM * DM], g_wil[DM * DM];
__device__ __nv_bfloat16 g_woh[DM * DM], g_wol[DM * DM];
__device__ __nv_bfloat16 g_fh[SQ * DM], g_fl[SQ * DM];

// ---------------------------------------------------------------------------
// Split fp32 -> bf16 hi + bf16 lo (lo = rn(v - f32(hi)))
// ---------------------------------------------------------------------------
__global__ __launch_bounds__(256)
void cvt_split(const float* __restrict__ src,
               __nv_bfloat16* __restrict__ hi,
               __nv_bfloat16* __restrict__ lo, int n)
{
    const int i = (blockIdx.x * 256 + threadIdx.x) * 4;
    if (i >= n) return;
    float4 v = *(const float4*)(src + i);
    __nv_bfloat16 h0 = __float2bfloat16(v.x);
    __nv_bfloat16 h1 = __float2bfloat16(v.y);
    __nv_bfloat16 h2 = __float2bfloat16(v.z);
    __nv_bfloat16 h3 = __float2bfloat16(v.w);
    __nv_bfloat162 hv0; hv0.x = h0; hv0.y = h1;
    __nv_bfloat162 hv1; hv1.x = h2; hv1.y = h3;
    __nv_bfloat162 lv0, lv1;
    lv0.x = __float2bfloat16(v.x - __bfloat162float(h0));
    lv0.y = __float2bfloat16(v.y - __bfloat162float(h1));
    lv1.x = __float2bfloat16(v.z - __bfloat162float(h2));
    lv1.y = __float2bfloat16(v.w - __bfloat162float(h3));
    *(__nv_bfloat162*)(hi + i)     = hv0;
    *(__nv_bfloat162*)(hi + i + 2) = hv1;
    *(__nv_bfloat162*)(lo + i)     = lv0;
    *(__nv_bfloat162*)(lo + i + 2) = lv1;
}

// ---------------------------------------------------------------------------
// bf16x3 NT GEMM, cp.async double-buffered.
// C[m,n] = sum_k A[m,k]*B[n,k]; A,B given as bf16 hi/lo pairs.
// Tile 128x128xBK32, 256 threads, 8 warps (2x4), warp tile 64x32,
// mma.m16n8k16: 4 mt x 4 nt x 3 splits per k16 step.
// smem row stride 40 bf16 (80B) -> conflict-free fragment LDS.
// ---------------------------------------------------------------------------
#define SROW 40
#define AELEM (128 * SROW)          // elems per array per buffer
#define BUFELEM (4 * AELEM)         // Ah, Al, Bh, Bl
#define GSMEM (2 * BUFELEM * 2)     // bytes: 81920

__device__ __forceinline__ void cp16(uint32_t sdst, const void* gsrc) {
    asm volatile("cp.async.cg.shared.global [%0], [%1], 16;" ::
                 "r"(sdst), "l"(gsrc));
}
__device__ __forceinline__ void cp_commit() {
    asm volatile("cp.async.commit_group;");
}
__device__ __forceinline__ void mma_bf16(float* c, const uint32_t* a, const uint32_t* b) {
    asm volatile(
        "mma.sync.aligned.m16n8k16.row.col.f32.bf16.bf16.f32 "
        "{%0,%1,%2,%3}, {%4,%5,%6,%7}, {%8,%9}, {%0,%1,%2,%3};"
        : "+f"(c[0]), "+f"(c[1]), "+f"(c[2]), "+f"(c[3])
        : "r"(a[0]), "r"(a[1]), "r"(a[2]), "r"(a[3]), "r"(b[0]), "r"(b[1]));
}

template <bool EPI>
__global__ __launch_bounds__(256, 1)
void gemm_bf16x3(const __nv_bfloat16* __restrict__ Ah,
                 const __nv_bfloat16* __restrict__ Al,
                 const __nv_bfloat16* __restrict__ Bh,
                 const __nv_bfloat16* __restrict__ Bl,
                 float* __restrict__ C,
                 const float* __restrict__ bias,
                 const float* __restrict__ resid)
{
    constexpr int KD = 1024, NC = 1024, NS = 32;   // 32 stages of BK=32

    extern __shared__ __nv_bfloat16 sm[];
    uint32_t sbase;
    asm("{ .reg .u64 t; cvta.to.shared.u64 t, %1; cvt.u32.u64 %0, t; }"
        : "=r"(sbase) : "l"(sm));

    const int t    = threadIdx.x;
    const int lane = t & 31;
    const int w    = t >> 5;
    const int wm   = w >> 2;
    const int wn   = w & 3;
    const int bm   = blockIdx.y;
    const int bn   = blockIdx.x;
    const int r4   = lane >> 2;
    const int c4   = lane & 3;

    const __nv_bfloat16* gsrc[4] = {
        Ah + (size_t)(bm * 128) * KD, Al + (size_t)(bm * 128) * KD,
        Bh + (size_t)(bn * 128) * KD, Bl + (size_t)(bn * 128) * KD };

    // cp.async chunk mapping: per array per stage, 512 x 16B chunks
    const int crow = t >> 2;              // rows t/4 and t/4+64
    const int c16  = t & 3;               // 16B unit within 64B row

    float acc[4][4][4];
#pragma unroll
    for (int i = 0; i < 4; i++)
#pragma unroll
        for (int j = 0; j < 4; j++)
#pragma unroll
            for (int q = 0; q < 4; q++) acc[i][j][q] = 0.f;

    auto issue_stage = [&](int ks, int buf) {
        const int k0 = ks * 32;
#pragma unroll
        for (int arr = 0; arr < 4; arr++) {
            const uint32_t sb = sbase + (uint32_t)(buf * BUFELEM + arr * AELEM) * 2;
#pragma unroll
            for (int j = 0; j < 2; j++) {
                const int row = crow + j * 64;
                cp16(sb + (uint32_t)(row * SROW + c16 * 8) * 2,
                     gsrc[arr] + (size_t)row * KD + k0 + c16 * 8);
            }
        }
        cp_commit();
    };

    issue_stage(0, 0);

    for (int ks = 0; ks < NS; ks++) {
        const int buf = ks & 1;
        if (ks + 1 < NS) {
            issue_stage(ks + 1, buf ^ 1);
            asm volatile("cp.async.wait_group 1;");
        } else {
            asm volatile("cp.async.wait_group 0;");
        }
        __syncthreads();

        const __nv_bfloat16* sAh = sm + buf * BUFELEM;
        const __nv_bfloat16* sAl = sAh + AELEM;
        const __nv_bfloat16* sBh = sAl + AELEM;
        const __nv_bfloat16* sBl = sBh + AELEM;

#pragma unroll
        for (int kk = 0; kk < 2; kk++) {
            const int kc = kk * 16 + 2 * c4;
            uint32_t bh[4][2], bl[4][2];
#pragma unroll
            for (int nt = 0; nt < 4; nt++) {
                const int n0 = wn * 32 + nt * 8 + r4;
                bh[nt][0] = *(const uint32_t*)(sBh + n0 * SROW + kc);
                bh[nt][1] = *(const uint32_t*)(sBh + n0 * SROW + kc + 8);
                bl[nt][0] = *(const uint32_t*)(sBl + n0 * SROW + kc);
                bl[nt][1] = *(const uint32_t*)(sBl + n0 * SROW + kc + 8);
            }
#pragma unroll
            for (int mt = 0; mt < 4; mt++) {
                const int m0 = wm * 64 + mt * 16 + r4;
                uint32_t ah[4], al[4];
                ah[0] = *(const uint32_t*)(sAh + m0 * SROW + kc);
                ah[1] = *(const uint32_t*)(sAh + (m0 + 8) * SROW + kc);
                ah[2] = *(const uint32_t*)(sAh + m0 * SROW + kc + 8);
                ah[3] = *(const uint32_t*)(sAh + (m0 + 8) * SROW + kc + 8);
                al[0] = *(const uint32_t*)(sAl + m0 * SROW + kc);
                al[1] = *(const uint32_t*)(sAl + (m0 + 8) * SROW + kc);
                al[2] = *(const uint32_t*)(sAl + m0 * SROW + kc + 8);
                al[3] = *(const uint32_t*)(sAl + (m0 + 8) * SROW + kc + 8);
#pragma unroll
                for (int nt = 0; nt < 4; nt++) {
                    mma_bf16(acc[mt][nt], ah, bh[nt]);
                    mma_bf16(acc[mt][nt], ah, bl[nt]);
                    mma_bf16(acc[mt][nt], al, bh[nt]);
                }
            }
        }
        __syncthreads();
    }

    // Epilogue
#pragma unroll
    for (int mt = 0; mt < 4; mt++) {
#pragma unroll
        for (int nt = 0; nt < 4; nt++) {
            const int row0 = bm * 128 + wm * 64 + mt * 16 + r4;
            const int col  = bn * 128 + wn * 32 + nt * 8 + c4 * 2;
            float2 v0 = make_float2(acc[mt][nt][0], acc[mt][nt][1]);
            float2 v1 = make_float2(acc[mt][nt][2], acc[mt][nt][3]);
            if (EPI) {
                float2 bv = *(const float2*)(bias + col);
                float2 r0 = *(const float2*)(resid + (size_t)row0 * NC + col);
                float2 r1 = *(const float2*)(resid + (size_t)(row0 + 8) * NC + col);
                v0.x += bv.x + r0.x;  v0.y += bv.y + r0.y;
                v1.x += bv.x + r1.x;  v1.y += bv.y + r1.y;
            }
            *(float2*)(C + (size_t)row0 * NC + col)       = v0;
            *(float2*)(C + (size_t)(row0 + 8) * NC + col) = v1;
        }
    }
}

// ---------------------------------------------------------------------------
// Attention-fusion: unchanged math; now emits fused as bf16 hi/lo.
// ---------------------------------------------------------------------------
__global__ __launch_bounds__(64)
void attn_kernel(const float* __restrict__ hbuf,
                 const int32_t* __restrict__ routes,
                 __nv_bfloat16* __restrict__ fh,
                 __nv_bfloat16* __restrict__ fl)
{
    const int s  = blockIdx.x;
    const int hh = blockIdx.y;
    const int t  = threadIdx.x;

    __shared__ float nbT[HDD][NK + 1];
    __shared__ float q[HDD];
    __shared__ float sc[NK];

    q[t] = hbuf[(size_t)s * DM + hh * HDD + t];
    __syncthreads();

    const int r = routes[(size_t)s * NK + t] & (SQ - 1);
    const float* np = hbuf + (size_t)r * DM + hh * HDD;
    float dot = 0.f;
#pragma unroll
    for (int d0 = 0; d0 < HDD; d0 += 4) {
        float4 v  = *(const float4*)(np + d0);
        float4 qv = *(const float4*)(q + d0);
        dot = fmaf(v.x, qv.x, dot);
        dot = fmaf(v.y, qv.y, dot);
        dot = fmaf(v.z, qv.z, dot);
        dot = fmaf(v.w, qv.w, dot);
        nbT[d0 + 0][t] = v.x;
        nbT[d0 + 1][t] = v.y;
        nbT[d0 + 2][t] = v.z;
        nbT[d0 + 3][t] = v.w;
    }
    sc[t] = dot * 0.125f;
    __syncthreads();

    float mx = -1e30f;
#pragma unroll
    for (int k = 0; k < NK; k++) mx = fmaxf(mx, sc[k]);
    const float wexp = expf(sc[t] - mx);
    __syncthreads();
    sc[t] = wexp;
    __syncthreads();

    float sum = 0.f, accv = 0.f;
#pragma unroll
    for (int k = 0; k < NK; k++) {
        const float wk = sc[k];
        sum  += wk;
        accv  = fmaf(wk, nbT[t][k], accv);
    }
    const float val = accv / sum;
    const size_t idx = (size_t)s * DM + hh * HDD + t;
    __nv_bfloat16 hv = __float2bfloat16(val);
    fh[idx] = hv;
    fl[idx] = __float2bfloat16(val - __bfloat162float(hv));
}

// ---------------------------------------------------------------------------
// Launch
// ---------------------------------------------------------------------------
extern "C" void kernel_launch(void* const* d_in, const int* in_sizes, int n_in,
                              void* d_out, int out_size)
{
    const float*   x      = nullptr;
    const int32_t* routes = nullptr;
    const float*   W_in   = nullptr;
    const float*   W_out  = nullptr;
    const float*   b_out  = nullptr;

    for (int i = 0; i < n_in; i++) {
        const int sz = in_sizes[i];
        if      (sz == SQ * DM)  { x = (const float*)d_in[i]; }
        else if (sz == SQ * NK)  { routes = (const int32_t*)d_in[i]; }
        else if (sz == DM * DM)  { if (!W_in) W_in = (const float*)d_in[i];
                                   else       W_out = (const float*)d_in[i]; }
        else if (sz == DM)       { b_out = (const float*)d_in[i]; }
    }
    float* out = (float*)d_out;

    float *hbuf;
    __nv_bfloat16 *xh, *xl, *wih, *wil, *woh, *wol, *fh, *fl;
    cudaGetSymbolAddress((void**)&hbuf, g_h);
    cudaGetSymbolAddress((void**)&xh,  g_xh);  cudaGetSymbolAddress((void**)&xl,  g_xl);
    cudaGetSymbolAddress((void**)&wih, g_wih); cudaGetSymbolAddress((void**)&wil, g_wil);
    cudaGetSymbolAddress((void**)&woh, g_woh); cudaGetSymbolAddress((void**)&wol, g_wol);
    cudaGetSymbolAddress((void**)&fh,  g_fh);  cudaGetSymbolAddress((void**)&fl,  g_fl);

    cudaFuncSetAttribute(gemm_bf16x3<false>,
                         cudaFuncAttributeMaxDynamicSharedMemorySize, GSMEM);
    cudaFuncSetAttribute(gemm_bf16x3<true>,
                         cudaFuncAttributeMaxDynamicSharedMemorySize, GSMEM);

    // Pre-split inputs into bf16 hi/lo
    cvt_split<<<SQ * DM / 1024, 256>>>(x, xh, xl, SQ * DM);
    cvt_split<<<DM * DM / 1024, 256>>>(W_in, wih, wil, DM * DM);
    cvt_split<<<DM * DM / 1024, 256>>>(W_out, woh, wol, DM * DM);

    dim3 gGemm(DM / 128, SQ / 128);   // (8, 16)

    gemm_bf16x3<false><<<gGemm, 256, GSMEM>>>(xh, xl, wih, wil, hbuf,
                                              nullptr, nullptr);
    attn_kernel<<<dim3(SQ, NH), 64>>>(hbuf, routes, fh, fl);
    gemm_bf16x3<true><<<gGemm, 256, GSMEM>>>(fh, fl, woh, wol, out, b_out, x);
}

// round 5
// speedup vs baseline: 2.0043x; 1.3520x over previous
#include <cuda_runtime.h>
#include <cuda_bf16.h>
#include <stdint.h>

#define SQ   2048
#define DM   1024
#define NH   16
#define HDD  64
#define NK   64

// fp32 hidden buffer (attn gathers from this)
__device__ float g_h[SQ * DM];
// bf16 hi/lo operand copies
__device__ __nv_bfloat16 g_xh[SQ * DM], g_xl[SQ * DM];
__device__ __nv_bfloat16 g_wih[DM * DM], g_wil[DM * DM];
__device__ __nv_bfloat16 g_woh[DM * DM], g_wol[DM * DM];
__device__ __nv_bfloat16 g_fh[SQ * DM], g_fl[SQ * DM];

// ---------------------------------------------------------------------------
// Split fp32 -> bf16 hi + bf16 lo
// ---------------------------------------------------------------------------
__global__ __launch_bounds__(256)
void cvt_split(const float* __restrict__ src,
               __nv_bfloat16* __restrict__ hi,
               __nv_bfloat16* __restrict__ lo, int n)
{
    const int i = (blockIdx.x * 256 + threadIdx.x) * 4;
    if (i >= n) return;
    float4 v = *(const float4*)(src + i);
    __nv_bfloat16 h0 = __float2bfloat16(v.x);
    __nv_bfloat16 h1 = __float2bfloat16(v.y);
    __nv_bfloat16 h2 = __float2bfloat16(v.z);
    __nv_bfloat16 h3 = __float2bfloat16(v.w);
    __nv_bfloat162 hv0; hv0.x = h0; hv0.y = h1;
    __nv_bfloat162 hv1; hv1.x = h2; hv1.y = h3;
    __nv_bfloat162 lv0, lv1;
    lv0.x = __float2bfloat16(v.x - __bfloat162float(h0));
    lv0.y = __float2bfloat16(v.y - __bfloat162float(h1));
    lv1.x = __float2bfloat16(v.z - __bfloat162float(h2));
    lv1.y = __float2bfloat16(v.w - __bfloat162float(h3));
    *(__nv_bfloat162*)(hi + i)     = hv0;
    *(__nv_bfloat162*)(hi + i + 2) = hv1;
    *(__nv_bfloat162*)(lo + i)     = lv0;
    *(__nv_bfloat162*)(lo + i + 2) = lv1;
}

// ---------------------------------------------------------------------------
// bf16x3 NT GEMM, cp.async double-buffered (unchanged from R4).
// ---------------------------------------------------------------------------
#define SROW 40
#define AELEM (128 * SROW)
#define BUFELEM (4 * AELEM)
#define GSMEM (2 * BUFELEM * 2)

__device__ __forceinline__ void cp16(uint32_t sdst, const void* gsrc) {
    asm volatile("cp.async.cg.shared.global [%0], [%1], 16;" ::
                 "r"(sdst), "l"(gsrc));
}
__device__ __forceinline__ void cp_commit() {
    asm volatile("cp.async.commit_group;");
}
__device__ __forceinline__ void mma_bf16(float* c, const uint32_t* a, const uint32_t* b) {
    asm volatile(
        "mma.sync.aligned.m16n8k16.row.col.f32.bf16.bf16.f32 "
        "{%0,%1,%2,%3}, {%4,%5,%6,%7}, {%8,%9}, {%0,%1,%2,%3};"
        : "+f"(c[0]), "+f"(c[1]), "+f"(c[2]), "+f"(c[3])
        : "r"(a[0]), "r"(a[1]), "r"(a[2]), "r"(a[3]), "r"(b[0]), "r"(b[1]));
}

template <bool EPI>
__global__ __launch_bounds__(256, 1)
void gemm_bf16x3(const __nv_bfloat16* __restrict__ Ah,
                 const __nv_bfloat16* __restrict__ Al,
                 const __nv_bfloat16* __restrict__ Bh,
                 const __nv_bfloat16* __restrict__ Bl,
                 float* __restrict__ C,
                 const float* __restrict__ bias,
                 const float* __restrict__ resid)
{
    constexpr int KD = 1024, NC = 1024, NS = 32;

    extern __shared__ __nv_bfloat16 sm[];
    uint32_t sbase;
    asm("{ .reg .u64 t; cvta.to.shared.u64 t, %1; cvt.u32.u64 %0, t; }"
        : "=r"(sbase) : "l"(sm));

    const int t    = threadIdx.x;
    const int lane = t & 31;
    const int w    = t >> 5;
    const int wm   = w >> 2;
    const int wn   = w & 3;
    const int bm   = blockIdx.y;
    const int bn   = blockIdx.x;
    const int r4   = lane >> 2;
    const int c4   = lane & 3;

    const __nv_bfloat16* gsrc[4] = {
        Ah + (size_t)(bm * 128) * KD, Al + (size_t)(bm * 128) * KD,
        Bh + (size_t)(bn * 128) * KD, Bl + (size_t)(bn * 128) * KD };

    const int crow = t >> 2;
    const int c16  = t & 3;

    float acc[4][4][4];
#pragma unroll
    for (int i = 0; i < 4; i++)
#pragma unroll
        for (int j = 0; j < 4; j++)
#pragma unroll
            for (int q = 0; q < 4; q++) acc[i][j][q] = 0.f;

    auto issue_stage = [&](int ks, int buf) {
        const int k0 = ks * 32;
#pragma unroll
        for (int arr = 0; arr < 4; arr++) {
            const uint32_t sb = sbase + (uint32_t)(buf * BUFELEM + arr * AELEM) * 2;
#pragma unroll
            for (int j = 0; j < 2; j++) {
                const int row = crow + j * 64;
                cp16(sb + (uint32_t)(row * SROW + c16 * 8) * 2,
                     gsrc[arr] + (size_t)row * KD + k0 + c16 * 8);
            }
        }
        cp_commit();
    };

    issue_stage(0, 0);

    for (int ks = 0; ks < NS; ks++) {
        const int buf = ks & 1;
        if (ks + 1 < NS) {
            issue_stage(ks + 1, buf ^ 1);
            asm volatile("cp.async.wait_group 1;");
        } else {
            asm volatile("cp.async.wait_group 0;");
        }
        __syncthreads();

        const __nv_bfloat16* sAh = sm + buf * BUFELEM;
        const __nv_bfloat16* sAl = sAh + AELEM;
        const __nv_bfloat16* sBh = sAl + AELEM;
        const __nv_bfloat16* sBl = sBh + AELEM;

#pragma unroll
        for (int kk = 0; kk < 2; kk++) {
            const int kc = kk * 16 + 2 * c4;
            uint32_t bh[4][2], bl[4][2];
#pragma unroll
            for (int nt = 0; nt < 4; nt++) {
                const int n0 = wn * 32 + nt * 8 + r4;
                bh[nt][0] = *(const uint32_t*)(sBh + n0 * SROW + kc);
                bh[nt][1] = *(const uint32_t*)(sBh + n0 * SROW + kc + 8);
                bl[nt][0] = *(const uint32_t*)(sBl + n0 * SROW + kc);
                bl[nt][1] = *(const uint32_t*)(sBl + n0 * SROW + kc + 8);
            }
#pragma unroll
            for (int mt = 0; mt < 4; mt++) {
                const int m0 = wm * 64 + mt * 16 + r4;
                uint32_t ah[4], al[4];
                ah[0] = *(const uint32_t*)(sAh + m0 * SROW + kc);
                ah[1] = *(const uint32_t*)(sAh + (m0 + 8) * SROW + kc);
                ah[2] = *(const uint32_t*)(sAh + m0 * SROW + kc + 8);
                ah[3] = *(const uint32_t*)(sAh + (m0 + 8) * SROW + kc + 8);
                al[0] = *(const uint32_t*)(sAl + m0 * SROW + kc);
                al[1] = *(const uint32_t*)(sAl + (m0 + 8) * SROW + kc);
                al[2] = *(const uint32_t*)(sAl + m0 * SROW + kc + 8);
                al[3] = *(const uint32_t*)(sAl + (m0 + 8) * SROW + kc + 8);
#pragma unroll
                for (int nt = 0; nt < 4; nt++) {
                    mma_bf16(acc[mt][nt], ah, bh[nt]);
                    mma_bf16(acc[mt][nt], ah, bl[nt]);
                    mma_bf16(acc[mt][nt], al, bh[nt]);
                }
            }
        }
        __syncthreads();
    }

#pragma unroll
    for (int mt = 0; mt < 4; mt++) {
#pragma unroll
        for (int nt = 0; nt < 4; nt++) {
            const int row0 = bm * 128 + wm * 64 + mt * 16 + r4;
            const int col  = bn * 128 + wn * 32 + nt * 8 + c4 * 2;
            float2 v0 = make_float2(acc[mt][nt][0], acc[mt][nt][1]);
            float2 v1 = make_float2(acc[mt][nt][2], acc[mt][nt][3]);
            if (EPI) {
                float2 bv = *(const float2*)(bias + col);
                float2 r0 = *(const float2*)(resid + (size_t)row0 * NC + col);
                float2 r1 = *(const float2*)(resid + (size_t)(row0 + 8) * NC + col);
                v0.x += bv.x + r0.x;  v0.y += bv.y + r0.y;
                v1.x += bv.x + r1.x;  v1.y += bv.y + r1.y;
            }
            *(float2*)(C + (size_t)row0 * NC + col)       = v0;
            *(float2*)(C + (size_t)(row0 + 8) * NC + col) = v1;
        }
    }
}

// ---------------------------------------------------------------------------
// Attention-fusion, coalesced gather version.
// Block = 64 threads per (s, head). Gather: 16 threads per neighbor row
// (256B contiguous) -> 4 wavefronts per warp LDG instead of 32.
// nb[k][d] stride 68 floats: conflict-free STS.128 (quarter-warps row-
// contiguous), LDS.128 score reads (4t mod 32 distinct), scalar column reads.
// ---------------------------------------------------------------------------
#define NBS 68
__global__ __launch_bounds__(64)
void attn_kernel(const float* __restrict__ hbuf,
                 const int32_t* __restrict__ routes,
                 __nv_bfloat16* __restrict__ fh,
                 __nv_bfloat16* __restrict__ fl)
{
    const int s  = blockIdx.x;
    const int hh = blockIdx.y;
    const int t  = threadIdx.x;

    __shared__ float nb[NK][NBS];
    __shared__ float q[HDD];
    __shared__ float sc[NK];
    __shared__ int   rt[NK];

    rt[t] = routes[(size_t)s * NK + t] & (SQ - 1);
    q[t]  = hbuf[(size_t)s * DM + hh * HDD + t];
    __syncthreads();

    // Cooperative gather: group g (of 4) loads row p*4+g, thread-in-group i
    // loads float4 #i of the 64-float row.
    const int g = t >> 4;      // 0..3
    const int i4 = (t & 15) * 4;
#pragma unroll
    for (int p = 0; p < 16; p++) {
        const int k = p * 4 + g;
        const float* np = hbuf + (size_t)rt[k] * DM + hh * HDD;
        *(float4*)&nb[k][i4] = *(const float4*)(np + i4);
    }
    __syncthreads();

    // Scores: thread t = neighbor t
    float dot = 0.f;
#pragma unroll
    for (int d0 = 0; d0 < HDD; d0 += 4) {
        float4 v  = *(const float4*)&nb[t][d0];
        float4 qv = *(const float4*)&q[d0];
        dot = fmaf(v.x, qv.x, dot);
        dot = fmaf(v.y, qv.y, dot);
        dot = fmaf(v.z, qv.z, dot);
        dot = fmaf(v.w, qv.w, dot);
    }
    sc[t] = dot * 0.125f;
    __syncthreads();

    float mx = -1e30f;
#pragma unroll
    for (int k = 0; k < NK; k++) mx = fmaxf(mx, sc[k]);
    const float wexp = expf(sc[t] - mx);
    __syncthreads();
    sc[t] = wexp;
    __syncthreads();

    // Weighted sum: thread t = head-dim d
    float sum = 0.f, accv = 0.f;
#pragma unroll
    for (int k = 0; k < NK; k++) {
        const float wk = sc[k];
        sum  += wk;
        accv  = fmaf(wk, nb[k][t], accv);
    }
    const float val = accv / sum;
    const size_t idx = (size_t)s * DM + hh * HDD + t;
    __nv_bfloat16 hv = __float2bfloat16(val);
    fh[idx] = hv;
    fl[idx] = __float2bfloat16(val - __bfloat162float(hv));
}

// ---------------------------------------------------------------------------
// Launch
// ---------------------------------------------------------------------------
extern "C" void kernel_launch(void* const* d_in, const int* in_sizes, int n_in,
                              void* d_out, int out_size)
{
    const float*   x      = nullptr;
    const int32_t* routes = nullptr;
    const float*   W_in   = nullptr;
    const float*   W_out  = nullptr;
    const float*   b_out  = nullptr;

    for (int i = 0; i < n_in; i++) {
        const int sz = in_sizes[i];
        if      (sz == SQ * DM)  { x = (const float*)d_in[i]; }
        else if (sz == SQ * NK)  { routes = (const int32_t*)d_in[i]; }
        else if (sz == DM * DM)  { if (!W_in) W_in = (const float*)d_in[i];
                                   else       W_out = (const float*)d_in[i]; }
        else if (sz == DM)       { b_out = (const float*)d_in[i]; }
    }
    float* out = (float*)d_out;

    float *hbuf;
    __nv_bfloat16 *xh, *xl, *wih, *wil, *woh, *wol, *fh, *fl;
    cudaGetSymbolAddress((void**)&hbuf, g_h);
    cudaGetSymbolAddress((void**)&xh,  g_xh);  cudaGetSymbolAddress((void**)&xl,  g_xl);
    cudaGetSymbolAddress((void**)&wih, g_wih); cudaGetSymbolAddress((void**)&wil, g_wil);
    cudaGetSymbolAddress((void**)&woh, g_woh); cudaGetSymbolAddress((void**)&wol, g_wol);
    cudaGetSymbolAddress((void**)&fh,  g_fh);  cudaGetSymbolAddress((void**)&fl,  g_fl);

    cudaFuncSetAttribute(gemm_bf16x3<false>,
                         cudaFuncAttributeMaxDynamicSharedMemorySize, GSMEM);
    cudaFuncSetAttribute(gemm_bf16x3<true>,
                         cudaFuncAttributeMaxDynamicSharedMemorySize, GSMEM);

    cvt_split<<<SQ * DM / 1024, 256>>>(x, xh, xl, SQ * DM);
    cvt_split<<<DM * DM / 1024, 256>>>(W_in, wih, wil, DM * DM);
    cvt_split<<<DM * DM / 1024, 256>>>(W_out, woh, wol, DM * DM);

    dim3 gGemm(DM / 128, SQ / 128);

    gemm_bf16x3<false><<<gGemm, 256, GSMEM>>>(xh, xl, wih, wil, hbuf,
                                              nullptr, nullptr);
    attn_kernel<<<dim3(SQ, NH), 64>>>(hbuf, routes, fh, fl);
    gemm_bf16x3<true><<<gGemm, 256, GSMEM>>>(fh, fl, woh, wol, out, b_out, x);
}